// round 4
// baseline (speedup 1.0000x reference)
#include <cuda_runtime.h>
#include <math.h>

#define B_   8
#define P_   128
#define N_   256
#define D_   128
#define DIN_ 256
#define M_   (B_*P_*N_)        // 262144 rows
#define ROWSTRIDE_ (N_*D_)     // 32768 floats between consecutive p for fixed (b,n)

typedef unsigned long long u64;

// ---------------- packed fp32x2 helpers (sm_103a FFMA2 path) ----------------
__device__ __forceinline__ u64 ffma2(u64 a, u64 b, u64 c) {
    u64 d; asm("fma.rn.f32x2 %0, %1, %2, %3;" : "=l"(d) : "l"(a), "l"(b), "l"(c)); return d;
}
__device__ __forceinline__ u64 fmul2(u64 a, u64 b) {
    u64 d; asm("mul.rn.f32x2 %0, %1, %2;" : "=l"(d) : "l"(a), "l"(b)); return d;
}
__device__ __forceinline__ u64 pack2(float x, float y) {
    u64 d; asm("mov.b64 %0, {%1, %2};" : "=l"(d) : "f"(x), "f"(y)); return d;
}
__device__ __forceinline__ float2 unpack2(u64 v) {
    float2 f; asm("mov.b64 {%0, %1}, %2;" : "=f"(f.x), "=f"(f.y) : "l"(v)); return f;
}

// ---------------- scratch (device globals; no allocation allowed) ----------------
__device__ float g_q[(size_t)M_ * D_];
__device__ float g_k[(size_t)M_ * D_];
__device__ float g_v[(size_t)M_ * D_];
__device__ float g_att[(size_t)M_ * D_];

__device__ __forceinline__ const float* resolve_in(const float* ext, int sel) {
    switch (sel) {
        case 0: return g_q;
        case 1: return g_k;
        case 2: return g_v;
        case 3: return g_att;
        default: return ext;
    }
}
__device__ __forceinline__ float* resolve_out(float* ext, int sel) {
    switch (sel) {
        case 0: return g_q;
        case 1: return g_k;
        case 2: return g_v;
        case 3: return g_att;
        default: return ext;
    }
}

// ---------------- SGEMM: C[M x 128] = act(A[M x KDIM] @ W[KDIM x 128] + bias) ----
// Tile: 128x128 per block, 256 threads, 8x8 microtile via FFMA2 (8x4 packed accs), BK=16.
// A smem tile stores DUPLICATED pairs {v,v} so the broadcast operand of the packed
// outer product loads directly from shared with no per-step pack MOVs.
template<int KDIM, bool RELU, bool CONCAT>
__global__ __launch_bounds__(256, 2)
void gemm_kernel(const float* __restrict__ Aext, const float* __restrict__ A2,
                 const float* __restrict__ W, const float* __restrict__ bias,
                 float* __restrict__ Oext, int asel, int osel)
{
    const float* A = resolve_in(Aext, asel);
    float* out = resolve_out(Oext, osel);

    __shared__ float2 As2[16][130];   // As2[k][row] = {a,a}  (row len 1040B, 16B aligned)
    __shared__ float  Bs[16][132];    // Bs[k][col]           (row len 528B, 16B aligned)

    const int tid = threadIdx.x;          // 0..255
    const int tx = tid & 15;              // col group (8 cols)
    const int ty = tid >> 4;              // row group (8 rows)
    const int row0 = blockIdx.x * 128;

    u64 acc[8][4];
#pragma unroll
    for (int i = 0; i < 8; i++)
#pragma unroll
        for (int j = 0; j < 4; j++) acc[i][j] = 0ull;   // {+0,+0}

    for (int kt = 0; kt < KDIM; kt += 16) {
        const float* Asrc = A;
        int kb = kt;
        if (CONCAT && kt >= 128) { Asrc = A2; kb = kt - 128; }

        // load A tile: 128 rows x 16 k (512 float4, 2 per thread), dup-transpose into As2
#pragma unroll
        for (int l = 0; l < 2; l++) {
            int id = tid * 2 + l;             // 0..511
            int r  = id >> 2;                 // 0..127
            int k4 = (id & 3) << 2;           // 0,4,8,12
            float4 v = *(const float4*)(Asrc + (size_t)(row0 + r) * 128 + kb + k4);
            As2[k4 + 0][r] = make_float2(v.x, v.x);
            As2[k4 + 1][r] = make_float2(v.y, v.y);
            As2[k4 + 2][r] = make_float2(v.z, v.z);
            As2[k4 + 3][r] = make_float2(v.w, v.w);
        }
        // load W tile: 16 k x 128 cols (512 float4, 2 per thread)
#pragma unroll
        for (int l = 0; l < 2; l++) {
            int id = tid * 2 + l;             // 0..511
            int kk = id >> 5;                 // 0..15
            int j4 = (id & 31) << 2;          // 0..124
            *(float4*)&Bs[kk][j4] = *(const float4*)(W + (size_t)(kt + kk) * 128 + j4);
        }
        __syncthreads();

#pragma unroll
        for (int kk = 0; kk < 16; kk++) {
            // A: 8 duplicated pairs (broadcast within 16-thread group -> no conflicts)
            u64 a2[8];
            {
                const ulonglong2* ap = (const ulonglong2*)&As2[kk][ty * 8];
                ulonglong2 p;
                p = ap[0]; a2[0] = p.x; a2[1] = p.y;
                p = ap[1]; a2[2] = p.x; a2[3] = p.y;
                p = ap[2]; a2[4] = p.x; a2[5] = p.y;
                p = ap[3]; a2[6] = p.x; a2[7] = p.y;
            }
            // B: 4 natural pairs (8 contiguous cols)
            u64 b2[4];
            {
                const ulonglong2* bp = (const ulonglong2*)&Bs[kk][tx * 8];
                ulonglong2 q0 = bp[0], q1 = bp[1];
                b2[0] = q0.x; b2[1] = q0.y; b2[2] = q1.x; b2[3] = q1.y;
            }
#pragma unroll
            for (int i = 0; i < 8; i++)
#pragma unroll
                for (int j = 0; j < 4; j++)
                    acc[i][j] = ffma2(a2[i], b2[j], acc[i][j]);
        }
        __syncthreads();
    }

    // epilogue: bias (+relu), vectorized store
    float bv[8];
#pragma unroll
    for (int j = 0; j < 8; j++) bv[j] = bias[tx * 8 + j];

#pragma unroll
    for (int i = 0; i < 8; i++) {
        int row = row0 + ty * 8 + i;
        float r[8];
#pragma unroll
        for (int j = 0; j < 4; j++) {
            float2 f = unpack2(acc[i][j]);
            float s0 = f.x + bv[2 * j];
            float s1 = f.y + bv[2 * j + 1];
            if (RELU) { s0 = fmaxf(s0, 0.f); s1 = fmaxf(s1, 0.f); }
            r[2 * j] = s0; r[2 * j + 1] = s1;
        }
        *(float4*)(out + (size_t)row * 128 + tx * 8)     = make_float4(r[0], r[1], r[2], r[3]);
        *(float4*)(out + (size_t)row * 128 + tx * 8 + 4) = make_float4(r[4], r[5], r[6], r[7]);
    }
}

// ---------------- attention: one block per (b, head, node) ----------------------
// thread t == query time index p. K/V staged in shared, Q row packed in registers,
// single-pass online softmax (causal: q <= t), inner loop in packed fp32x2.
__global__ __launch_bounds__(128)
void attn_kernel()
{
    const int n  = blockIdx.x;        // 0..255
    const int bh = blockIdx.y;        // 0..63
    const int b  = bh >> 3;
    const int h  = bh & 7;
    const int t  = threadIdx.x;       // query time p, 0..127

    __shared__ float Ks[128][16];     // rows 64B aligned
    __shared__ float Vs[128][16];

    // base offset of (b, p=0, n) row at this head's slice
    const size_t base = ((size_t)(b * P_) * N_ + n) * D_ + h * 16;

    // cooperative K/V load: 128 rows x 16 floats each = 512 float4 per tensor
#pragma unroll
    for (int i = 0; i < 4; i++) {
        int id = t + i * 128;          // 0..511
        int r  = id >> 2;              // key time index
        int d4 = (id & 3) << 2;        // 0,4,8,12
        size_t g = base + (size_t)r * ROWSTRIDE_ + d4;
        *(float4*)&Ks[r][d4] = *(const float4*)&g_k[g];
        *(float4*)&Vs[r][d4] = *(const float4*)&g_v[g];
    }

    // Q row for this thread, packed into 8 fp32x2 pairs
    u64 q2[8];
#pragma unroll
    for (int c = 0; c < 4; c++) {
        ulonglong2 p = *(const ulonglong2*)&g_q[base + (size_t)t * ROWSTRIDE_ + c * 4];
        q2[2 * c] = p.x; q2[2 * c + 1] = p.y;
    }
    __syncthreads();

    float m = -1e30f, denom = 0.f;
    u64 o2[8];
#pragma unroll
    for (int d = 0; d < 8; d++) o2[d] = 0ull;

    for (int q = 0; q <= t; q++) {
        const ulonglong2* kp = (const ulonglong2*)&Ks[q][0];   // uniform addr -> broadcast
        ulonglong2 ka = kp[0], kb = kp[1], kc = kp[2], kd = kp[3];
        u64 s2 = fmul2(q2[0], ka.x);
        s2 = ffma2(q2[1], ka.y, s2);
        s2 = ffma2(q2[2], kb.x, s2);
        s2 = ffma2(q2[3], kb.y, s2);
        s2 = ffma2(q2[4], kc.x, s2);
        s2 = ffma2(q2[5], kc.y, s2);
        s2 = ffma2(q2[6], kd.x, s2);
        s2 = ffma2(q2[7], kd.y, s2);
        float2 sf = unpack2(s2);
        float s = (sf.x + sf.y) * 0.25f;   // 1/sqrt(d_head=16)

        if (s > m) {
            float scale = __expf(m - s);
            denom *= scale;
            u64 sc2 = pack2(scale, scale);
#pragma unroll
            for (int d = 0; d < 8; d++) o2[d] = fmul2(o2[d], sc2);
            m = s;
        }
        float w = __expf(s - m);
        denom += w;
        u64 w2 = pack2(w, w);

        const ulonglong2* vp = (const ulonglong2*)&Vs[q][0];
        ulonglong2 va = vp[0], vb = vp[1], vc = vp[2], vd = vp[3];
        o2[0] = ffma2(w2, va.x, o2[0]);
        o2[1] = ffma2(w2, va.y, o2[1]);
        o2[2] = ffma2(w2, vb.x, o2[2]);
        o2[3] = ffma2(w2, vb.y, o2[3]);
        o2[4] = ffma2(w2, vc.x, o2[4]);
        o2[5] = ffma2(w2, vc.y, o2[5]);
        o2[6] = ffma2(w2, vd.x, o2[6]);
        o2[7] = ffma2(w2, vd.y, o2[7]);
    }

    float inv = 1.f / denom;
    u64 inv2 = pack2(inv, inv);
    size_t ob = base + (size_t)t * ROWSTRIDE_;
#pragma unroll
    for (int c = 0; c < 4; c++) {
        float2 f0 = unpack2(fmul2(o2[2 * c], inv2));
        float2 f1 = unpack2(fmul2(o2[2 * c + 1], inv2));
        *(float4*)&g_att[ob + c * 4] = make_float4(f0.x, f0.y, f1.x, f1.y);
    }
}

// ---------------- launch -------------------------------------------------------
extern "C" void kernel_launch(void* const* d_in, const int* in_sizes, int n_in,
                              void* d_out, int out_size)
{
    const float* X   = (const float*)d_in[0];
    const float* STE = (const float*)d_in[1];
    const float* Wq  = (const float*)d_in[2];
    const float* bq  = (const float*)d_in[3];
    const float* Wk  = (const float*)d_in[4];
    const float* bk  = (const float*)d_in[5];
    const float* Wv  = (const float*)d_in[6];
    const float* bv  = (const float*)d_in[7];
    const float* W1  = (const float*)d_in[8];
    const float* b1  = (const float*)d_in[9];
    const float* W2  = (const float*)d_in[10];
    const float* b2  = (const float*)d_in[11];
    float* out = (float*)d_out;

    const int nblk = M_ / 128;   // 2048

    // QKV projections: C = relu(concat(X,STE) @ W + b)
    gemm_kernel<256, true, true><<<nblk, 256>>>(X, STE, Wq, bq, nullptr, -1, 0);
    gemm_kernel<256, true, true><<<nblk, 256>>>(X, STE, Wk, bk, nullptr, -1, 1);
    gemm_kernel<256, true, true><<<nblk, 256>>>(X, STE, Wv, bv, nullptr, -1, 2);

    // causal attention per (b, head, node)
    attn_kernel<<<dim3(N_, B_ * 8), 128>>>();

    // output MLP: relu(att @ W1 + b1) @ W2 + b2
    gemm_kernel<128, true,  false><<<nblk, 256>>>(nullptr, nullptr, W1, b1, nullptr, 3, 0);
    gemm_kernel<128, false, false><<<nblk, 256>>>(nullptr, nullptr, W2, b2, out, 0, -1);
}

// round 7
// speedup vs baseline: 1.9047x; 1.9047x over previous
#include <cuda_runtime.h>
#include <cuda_bf16.h>
#include <math.h>
#include <stdint.h>

#define B_   8
#define P_   128
#define N_   256
#define D_   128
#define M_   (B_*P_*N_)        // 262144 rows
#define ROWSTRIDE_ (N_*D_)     // 32768 floats between consecutive p for fixed (b,n)

// ---------------- scratch (device globals; no allocation allowed) ----------------
__device__ float g_q[(size_t)M_ * D_];
__device__ float g_k[(size_t)M_ * D_];
__device__ float g_v[(size_t)M_ * D_];
__device__ float g_att[(size_t)M_ * D_];
__device__ float g_h[(size_t)M_ * D_];
// weights transposed to [n][k] and bf16-split. layout: Wq(32768) Wk Wv W1(16384) W2
__device__ __align__(16) __nv_bfloat16 g_wh[131072];
__device__ __align__(16) __nv_bfloat16 g_wl[131072];

__device__ __forceinline__ const float* resolve_in(const float* ext, int sel) {
    switch (sel) {
        case 0: return g_q;
        case 1: return g_k;
        case 2: return g_v;
        case 3: return g_att;
        case 4: return g_h;
        default: return ext;
    }
}
__device__ __forceinline__ float* resolve_out(float* ext, int sel) {
    switch (sel) {
        case 0: return g_q;
        case 1: return g_k;
        case 2: return g_v;
        case 3: return g_att;
        case 4: return g_h;
        default: return ext;
    }
}

// ---------------- helpers ----------------
__device__ __forceinline__ uint32_t smem_u32(const void* p) {
    uint32_t a;
    asm("{ .reg .u64 t; cvta.to.shared.u64 t, %1; cvt.u32.u64 %0, t; }" : "=r"(a) : "l"(p));
    return a;
}
__device__ __forceinline__ void split_bf16(float x, uint16_t& h, uint16_t& l) {
    __nv_bfloat16 hb = __float2bfloat16(x);
    __nv_bfloat16 lb = __float2bfloat16(x - __bfloat162float(hb));
    h = __bfloat16_as_ushort(hb);
    l = __bfloat16_as_ushort(lb);
}
__device__ __forceinline__ void ldmatrix_x4(uint32_t* r, uint32_t addr) {
    asm volatile("ldmatrix.sync.aligned.m8n8.x4.shared.b16 {%0,%1,%2,%3}, [%4];"
                 : "=r"(r[0]), "=r"(r[1]), "=r"(r[2]), "=r"(r[3]) : "r"(addr));
}
__device__ __forceinline__ void mma_bf16(float* d, const uint32_t* a, const uint32_t* b) {
    asm volatile(
        "mma.sync.aligned.m16n8k16.row.col.f32.bf16.bf16.f32 "
        "{%0,%1,%2,%3}, {%4,%5,%6,%7}, {%8,%9}, {%0,%1,%2,%3};"
        : "+f"(d[0]), "+f"(d[1]), "+f"(d[2]), "+f"(d[3])
        : "r"(a[0]), "r"(a[1]), "r"(a[2]), "r"(a[3]), "r"(b[0]), "r"(b[1]));
}

// ---------------- convert weights: W[k][n] fp32 -> transposed split bf16 ----------
__global__ void convert_w(const float* __restrict__ Wq, const float* __restrict__ Wk,
                          const float* __restrict__ Wv, const float* __restrict__ W1,
                          const float* __restrict__ W2)
{
    int id = blockIdx.x * 256 + threadIdx.x;      // < 131072
    const float* src; int K, n, k; size_t dofs;
    if (id < 98304) {
        int wi = id >> 15, rem = id & 32767;
        k = rem >> 7; n = rem & 127; K = 256;
        src = (wi == 0) ? Wq : (wi == 1) ? Wk : Wv;
        dofs = (size_t)wi * 32768;
    } else {
        int r2 = id - 98304;
        int wi = r2 >> 14, rem = r2 & 16383;
        k = rem >> 7; n = rem & 127; K = 128;
        src = wi ? W2 : W1;
        dofs = 98304 + (size_t)wi * 16384;
    }
    float x = src[(size_t)k * 128 + n];
    uint16_t h, l;
    split_bf16(x, h, l);
    size_t d = dofs + (size_t)n * K + k;
    ((uint16_t*)g_wh)[d] = h;
    ((uint16_t*)g_wl)[d] = l;
}

// ---------------- HMMA split-bf16 GEMM -----------------------------------------
// C[128x128 per CTA] = act(A[M x KDIM] @ W[KDIM x 128] + bias)
// A fp32 in gmem (optionally concat of two 128-col tensors), split to bf16 hi/lo
// in-kernel. W pre-transposed split bf16 [n][k]. C ~= Ah@Wh + Ah@Wl + Al@Wh.
#define PADK 40    // 32 + 8 bf16 pad -> 80B row stride, conflict-free ldmatrix

template<int KDIM, bool RELU, bool CONCAT>
__global__ __launch_bounds__(256)
void hmma_gemm(const float* __restrict__ Aext, const float* __restrict__ A2,
               int asel, int woff,
               const float* __restrict__ bias,
               float* __restrict__ Oext, int osel)
{
    const float* A = resolve_in(Aext, asel);
    float* out = resolve_out(Oext, osel);
    const __nv_bfloat16* Wh = g_wh + woff;
    const __nv_bfloat16* Wl = g_wl + woff;

    __shared__ __align__(16) __nv_bfloat16 sAh[128 * PADK];
    __shared__ __align__(16) __nv_bfloat16 sAl[128 * PADK];
    __shared__ __align__(16) __nv_bfloat16 sBh[128 * PADK];
    __shared__ __align__(16) __nv_bfloat16 sBl[128 * PADK];

    const int tid  = threadIdx.x;
    const int lane = tid & 31;
    const int wid  = tid >> 5;
    const int wm   = (wid & 1) * 64;        // warp row offset
    const int wn   = (wid >> 1) * 32;       // warp col offset
    const int row0 = blockIdx.x * 128;

    const uint32_t ah_base = smem_u32(sAh);
    const uint32_t al_base = smem_u32(sAl);
    const uint32_t bh_base = smem_u32(sBh);
    const uint32_t bl_base = smem_u32(sBl);

    float acc[4][4][4];
#pragma unroll
    for (int i = 0; i < 4; i++)
#pragma unroll
        for (int j = 0; j < 4; j++)
#pragma unroll
            for (int r = 0; r < 4; r++) acc[i][j][r] = 0.f;

    const int lr = tid >> 1;              // 0..127 (row for loads)
    const int lh = (tid & 1) * 16;        // k half offset

    for (int kt = 0; kt < KDIM; kt += 32) {
        // ---- stage A (fp32 -> split bf16) ----
        {
            const float* Asrc = A;
            int kb = kt;
            if (CONCAT && kt >= 128) { Asrc = A2; kb = kt - 128; }
            const float4* src = (const float4*)(Asrc + (size_t)(row0 + lr) * 128 + kb + lh);
            float v[16];
            float4 f0 = src[0], f1 = src[1], f2 = src[2], f3 = src[3];
            v[0]=f0.x; v[1]=f0.y; v[2]=f0.z; v[3]=f0.w;
            v[4]=f1.x; v[5]=f1.y; v[6]=f1.z; v[7]=f1.w;
            v[8]=f2.x; v[9]=f2.y; v[10]=f2.z; v[11]=f2.w;
            v[12]=f3.x; v[13]=f3.y; v[14]=f3.z; v[15]=f3.w;
            uint32_t hp[8], lp[8];
#pragma unroll
            for (int j = 0; j < 8; j++) {
                uint16_t h0, l0, h1, l1;
                split_bf16(v[2*j],   h0, l0);
                split_bf16(v[2*j+1], h1, l1);
                hp[j] = (uint32_t)h0 | ((uint32_t)h1 << 16);
                lp[j] = (uint32_t)l0 | ((uint32_t)l1 << 16);
            }
            int e = lr * PADK + lh;
            *(uint4*)((uint16_t*)sAh + e)     = make_uint4(hp[0], hp[1], hp[2], hp[3]);
            *(uint4*)((uint16_t*)sAh + e + 8) = make_uint4(hp[4], hp[5], hp[6], hp[7]);
            *(uint4*)((uint16_t*)sAl + e)     = make_uint4(lp[0], lp[1], lp[2], lp[3]);
            *(uint4*)((uint16_t*)sAl + e + 8) = make_uint4(lp[4], lp[5], lp[6], lp[7]);
        }
        // ---- stage W (already bf16, copy 16 elems per thread per matrix) ----
        {
            size_t g = (size_t)lr * KDIM + kt + lh;
            int e = lr * PADK + lh;
            const uint4* wh4 = (const uint4*)(Wh + g);
            const uint4* wl4 = (const uint4*)(Wl + g);
            *(uint4*)((uint16_t*)sBh + e)     = wh4[0];
            *(uint4*)((uint16_t*)sBh + e + 8) = wh4[1];
            *(uint4*)((uint16_t*)sBl + e)     = wl4[0];
            *(uint4*)((uint16_t*)sBl + e + 8) = wl4[1];
        }
        __syncthreads();

        // ---- 2 k16 sub-steps ----
#pragma unroll
        for (int ks = 0; ks < 2; ks++) {
            const int k0 = ks * 16;
            // A fragments (hi/lo), 4 m-tiles
            uint32_t fah[4][4], fal[4][4];
#pragma unroll
            for (int mi = 0; mi < 4; mi++) {
                uint32_t off = (uint32_t)((wm + mi * 16 + (lane & 15)) * PADK
                                          + k0 + ((lane >> 4) << 3)) * 2;
                ldmatrix_x4(fah[mi], ah_base + off);
                ldmatrix_x4(fal[mi], al_base + off);
            }
            // B fragments (hi/lo), 4 n-tiles via 2 x4 loads each
            uint32_t fbh[4][2], fbl[4][2];
#pragma unroll
            for (int njp = 0; njp < 2; njp++) {
                uint32_t off = (uint32_t)((wn + njp * 16 + ((lane >> 4) << 3) + (lane & 7)) * PADK
                                          + k0 + (((lane >> 3) & 1) << 3)) * 2;
                uint32_t t[4];
                ldmatrix_x4(t, bh_base + off);
                fbh[2*njp][0] = t[0]; fbh[2*njp][1] = t[1];
                fbh[2*njp+1][0] = t[2]; fbh[2*njp+1][1] = t[3];
                ldmatrix_x4(t, bl_base + off);
                fbl[2*njp][0] = t[0]; fbl[2*njp][1] = t[1];
                fbl[2*njp+1][0] = t[2]; fbl[2*njp+1][1] = t[3];
            }
            // 3-term split MMA
#pragma unroll
            for (int mi = 0; mi < 4; mi++)
#pragma unroll
                for (int ni = 0; ni < 4; ni++) {
                    mma_bf16(acc[mi][ni], fah[mi], fbh[ni]);
                    mma_bf16(acc[mi][ni], fah[mi], fbl[ni]);
                    mma_bf16(acc[mi][ni], fal[mi], fbh[ni]);
                }
        }
        __syncthreads();
    }

    // ---- epilogue: bias (+relu), write fp32 ----
#pragma unroll
    for (int mi = 0; mi < 4; mi++) {
#pragma unroll
        for (int ni = 0; ni < 4; ni++) {
            int r0 = row0 + wm + mi * 16 + (lane >> 2);
            int c  = wn + ni * 8 + ((lane & 3) << 1);
            float b0 = bias[c], b1 = bias[c + 1];
            float v00 = acc[mi][ni][0] + b0, v01 = acc[mi][ni][1] + b1;
            float v10 = acc[mi][ni][2] + b0, v11 = acc[mi][ni][3] + b1;
            if (RELU) {
                v00 = fmaxf(v00, 0.f); v01 = fmaxf(v01, 0.f);
                v10 = fmaxf(v10, 0.f); v11 = fmaxf(v11, 0.f);
            }
            *(float2*)&out[(size_t)r0 * 128 + c]       = make_float2(v00, v01);
            *(float2*)&out[(size_t)(r0 + 8) * 128 + c] = make_float2(v10, v11);
        }
    }
}

// ---------------- attention: one block per (b, head, node) ----------------------
// (known-good R2 kernel) thread t == query time p; K/V in shared; online softmax.
__global__ __launch_bounds__(128)
void attn_kernel()
{
    const int n  = blockIdx.x;
    const int bh = blockIdx.y;
    const int b  = bh >> 3;
    const int h  = bh & 7;
    const int t  = threadIdx.x;

    __shared__ float Ks[128][16];
    __shared__ float Vs[128][16];

    const size_t base = ((size_t)(b * P_) * N_ + n) * D_ + h * 16;

#pragma unroll
    for (int i = 0; i < 4; i++) {
        int id = t + i * 128;
        int r  = id >> 2;
        int d4 = (id & 3) << 2;
        size_t g = base + (size_t)r * ROWSTRIDE_ + d4;
        *(float4*)&Ks[r][d4] = *(const float4*)&g_k[g];
        *(float4*)&Vs[r][d4] = *(const float4*)&g_v[g];
    }

    float qr[16];
#pragma unroll
    for (int d4 = 0; d4 < 16; d4 += 4) {
        float4 v = *(const float4*)&g_q[base + (size_t)t * ROWSTRIDE_ + d4];
        qr[d4 + 0] = v.x; qr[d4 + 1] = v.y; qr[d4 + 2] = v.z; qr[d4 + 3] = v.w;
    }
    __syncthreads();

    float m = -1e30f, denom = 0.f;
    float o[16];
#pragma unroll
    for (int d = 0; d < 16; d++) o[d] = 0.f;

    for (int q = 0; q <= t; q++) {
        float4 k0 = *(const float4*)&Ks[q][0];
        float4 k1 = *(const float4*)&Ks[q][4];
        float4 k2 = *(const float4*)&Ks[q][8];
        float4 k3 = *(const float4*)&Ks[q][12];
        float s = qr[0] * k0.x;
        s = fmaf(qr[1],  k0.y, s); s = fmaf(qr[2],  k0.z, s); s = fmaf(qr[3],  k0.w, s);
        s = fmaf(qr[4],  k1.x, s); s = fmaf(qr[5],  k1.y, s); s = fmaf(qr[6],  k1.z, s); s = fmaf(qr[7],  k1.w, s);
        s = fmaf(qr[8],  k2.x, s); s = fmaf(qr[9],  k2.y, s); s = fmaf(qr[10], k2.z, s); s = fmaf(qr[11], k2.w, s);
        s = fmaf(qr[12], k3.x, s); s = fmaf(qr[13], k3.y, s); s = fmaf(qr[14], k3.z, s); s = fmaf(qr[15], k3.w, s);
        s *= 0.25f;

        if (s > m) {
            float scale = __expf(m - s);
            denom *= scale;
#pragma unroll
            for (int d = 0; d < 16; d++) o[d] *= scale;
            m = s;
        }
        float w = __expf(s - m);
        denom += w;

        float4 v0 = *(const float4*)&Vs[q][0];
        float4 v1 = *(const float4*)&Vs[q][4];
        float4 v2 = *(const float4*)&Vs[q][8];
        float4 v3 = *(const float4*)&Vs[q][12];
        o[0]  = fmaf(w, v0.x, o[0]);  o[1]  = fmaf(w, v0.y, o[1]);
        o[2]  = fmaf(w, v0.z, o[2]);  o[3]  = fmaf(w, v0.w, o[3]);
        o[4]  = fmaf(w, v1.x, o[4]);  o[5]  = fmaf(w, v1.y, o[5]);
        o[6]  = fmaf(w, v1.z, o[6]);  o[7]  = fmaf(w, v1.w, o[7]);
        o[8]  = fmaf(w, v2.x, o[8]);  o[9]  = fmaf(w, v2.y, o[9]);
        o[10] = fmaf(w, v2.z, o[10]); o[11] = fmaf(w, v2.w, o[11]);
        o[12] = fmaf(w, v3.x, o[12]); o[13] = fmaf(w, v3.y, o[13]);
        o[14] = fmaf(w, v3.z, o[14]); o[15] = fmaf(w, v3.w, o[15]);
    }

    float inv = 1.f / denom;
    size_t ob = base + (size_t)t * ROWSTRIDE_;
    *(float4*)&g_att[ob + 0]  = make_float4(o[0] * inv,  o[1] * inv,  o[2] * inv,  o[3] * inv);
    *(float4*)&g_att[ob + 4]  = make_float4(o[4] * inv,  o[5] * inv,  o[6] * inv,  o[7] * inv);
    *(float4*)&g_att[ob + 8]  = make_float4(o[8] * inv,  o[9] * inv,  o[10] * inv, o[11] * inv);
    *(float4*)&g_att[ob + 12] = make_float4(o[12] * inv, o[13] * inv, o[14] * inv, o[15] * inv);
}

// ---------------- launch -------------------------------------------------------
extern "C" void kernel_launch(void* const* d_in, const int* in_sizes, int n_in,
                              void* d_out, int out_size)
{
    const float* X   = (const float*)d_in[0];
    const float* STE = (const float*)d_in[1];
    const float* Wq  = (const float*)d_in[2];
    const float* bq  = (const float*)d_in[3];
    const float* Wk  = (const float*)d_in[4];
    const float* bk  = (const float*)d_in[5];
    const float* Wv  = (const float*)d_in[6];
    const float* bv  = (const float*)d_in[7];
    const float* W1  = (const float*)d_in[8];
    const float* b1  = (const float*)d_in[9];
    const float* W2  = (const float*)d_in[10];
    const float* b2  = (const float*)d_in[11];
    float* out = (float*)d_out;

    const int nblk = M_ / 128;   // 2048

    // weight preprocessing (transpose + bf16 split)
    convert_w<<<512, 256>>>(Wq, Wk, Wv, W1, W2);

    // QKV projections on HMMA (bf16x3)
    hmma_gemm<256, true, true><<<nblk, 256>>>(X, STE, -1, 0,      bq, nullptr, 0);
    hmma_gemm<256, true, true><<<nblk, 256>>>(X, STE, -1, 32768,  bk, nullptr, 1);
    hmma_gemm<256, true, true><<<nblk, 256>>>(X, STE, -1, 65536,  bv, nullptr, 2);

    // causal attention per (b, head, node)
    attn_kernel<<<dim3(N_, B_ * 8), 128>>>();

    // output MLP on HMMA
    hmma_gemm<128, true,  false><<<nblk, 256>>>(nullptr, nullptr, 3, 98304,  b1, nullptr, 4);
    hmma_gemm<128, false, false><<<nblk, 256>>>(nullptr, nullptr, 4, 114688, b2, out, -1);
}

// round 8
// speedup vs baseline: 1.9190x; 1.0075x over previous
#include <cuda_runtime.h>
#include <cuda_bf16.h>
#include <math.h>
#include <stdint.h>

#define B_   8
#define P_   128
#define N_   256
#define D_   128
#define M_   (B_*P_*N_)        // 262144 rows
#define ROWSTRIDE_ (N_*D_)     // 32768 floats between consecutive p for fixed (b,n)

// ---------------- scratch (device globals; no allocation allowed) ----------------
__device__ __align__(16) __nv_bfloat16 g_a_hi[(size_t)M_ * 256];
__device__ __align__(16) __nv_bfloat16 g_a_lo[(size_t)M_ * 256];
__device__ float g_q[(size_t)M_ * D_];
__device__ float g_k[(size_t)M_ * D_];
__device__ float g_v[(size_t)M_ * D_];
__device__ __align__(16) __nv_bfloat16 g_att_hi[(size_t)M_ * D_];
__device__ __align__(16) __nv_bfloat16 g_att_lo[(size_t)M_ * D_];
__device__ __align__(16) __nv_bfloat16 g_h_hi[(size_t)M_ * D_];
__device__ __align__(16) __nv_bfloat16 g_h_lo[(size_t)M_ * D_];
// weights transposed to [n][k], bf16-split. layout: Wq(32768) Wk Wv W1(16384) W2
__device__ __align__(16) __nv_bfloat16 g_wh[131072];
__device__ __align__(16) __nv_bfloat16 g_wl[131072];

__device__ __forceinline__ const __nv_bfloat16* resolve_ah(int s) {
    return s == 0 ? g_a_hi : s == 1 ? g_att_hi : g_h_hi;
}
__device__ __forceinline__ const __nv_bfloat16* resolve_al(int s) {
    return s == 0 ? g_a_lo : s == 1 ? g_att_lo : g_h_lo;
}
__device__ __forceinline__ float* resolve_o32(float* ext, int s) {
    return s == 0 ? g_q : s == 1 ? g_k : s == 2 ? g_v : ext;
}

// ---------------- helpers ----------------
__device__ __forceinline__ uint32_t smem_u32(const void* p) {
    uint32_t a;
    asm("{ .reg .u64 t; cvta.to.shared.u64 t, %1; cvt.u32.u64 %0, t; }" : "=r"(a) : "l"(p));
    return a;
}
__device__ __forceinline__ void split_bf16(float x, uint16_t& h, uint16_t& l) {
    __nv_bfloat16 hb = __float2bfloat16(x);
    __nv_bfloat16 lb = __float2bfloat16(x - __bfloat162float(hb));
    h = __bfloat16_as_ushort(hb);
    l = __bfloat16_as_ushort(lb);
}
__device__ __forceinline__ void ldmatrix_x4(uint32_t* r, uint32_t addr) {
    asm volatile("ldmatrix.sync.aligned.m8n8.x4.shared.b16 {%0,%1,%2,%3}, [%4];"
                 : "=r"(r[0]), "=r"(r[1]), "=r"(r[2]), "=r"(r[3]) : "r"(addr));
}
__device__ __forceinline__ void mma_bf16(float* d, const uint32_t* a, const uint32_t* b) {
    asm volatile(
        "mma.sync.aligned.m16n8k16.row.col.f32.bf16.bf16.f32 "
        "{%0,%1,%2,%3}, {%4,%5,%6,%7}, {%8,%9}, {%0,%1,%2,%3};"
        : "+f"(d[0]), "+f"(d[1]), "+f"(d[2]), "+f"(d[3])
        : "r"(a[0]), "r"(a[1]), "r"(a[2]), "r"(a[3]), "r"(b[0]), "r"(b[1]));
}
__device__ __forceinline__ void cp_async16(uint32_t dst, const void* src) {
    asm volatile("cp.async.ca.shared.global [%0], [%1], 16;" :: "r"(dst), "l"(src));
}
__device__ __forceinline__ void cp_commit() {
    asm volatile("cp.async.commit_group;" ::: "memory");
}
__device__ __forceinline__ void cp_wait0() {
    asm volatile("cp.async.wait_group 0;" ::: "memory");
}
__device__ __forceinline__ void cp_wait1() {
    asm volatile("cp.async.wait_group 1;" ::: "memory");
}

// ---------------- convert weights: W[k][n] fp32 -> transposed split bf16 ----------
__global__ void convert_w(const float* __restrict__ Wq, const float* __restrict__ Wk,
                          const float* __restrict__ Wv, const float* __restrict__ W1,
                          const float* __restrict__ W2)
{
    int id = blockIdx.x * 256 + threadIdx.x;      // < 131072
    const float* src; int K, n, k; size_t dofs;
    if (id < 98304) {
        int wi = id >> 15, rem = id & 32767;
        k = rem >> 7; n = rem & 127; K = 256;
        src = (wi == 0) ? Wq : (wi == 1) ? Wk : Wv;
        dofs = (size_t)wi * 32768;
    } else {
        int r2 = id - 98304;
        int wi = r2 >> 14, rem = r2 & 16383;
        k = rem >> 7; n = rem & 127; K = 128;
        src = wi ? W2 : W1;
        dofs = 98304 + (size_t)wi * 16384;
    }
    float x = src[(size_t)k * 128 + n];
    uint16_t h, l;
    split_bf16(x, h, l);
    size_t d = dofs + (size_t)n * K + k;
    ((uint16_t*)g_wh)[d] = h;
    ((uint16_t*)g_wl)[d] = l;
}

// ---------------- convert activations: concat(X,STE) -> split bf16 [M x 256] -----
__global__ void convert_a(const float* __restrict__ X, const float* __restrict__ STE)
{
    size_t id = (size_t)blockIdx.x * 256 + threadIdx.x;   // one per 8 elements
    int row = (int)(id >> 5);
    int c8  = (int)(id & 31) << 3;
    const float* src = (c8 < 128) ? (X + (size_t)row * 128 + c8)
                                  : (STE + (size_t)row * 128 + (c8 - 128));
    float4 v0 = ((const float4*)src)[0];
    float4 v1 = ((const float4*)src)[1];
    float vv[8] = {v0.x, v0.y, v0.z, v0.w, v1.x, v1.y, v1.z, v1.w};
    uint32_t hp[4], lp[4];
#pragma unroll
    for (int j = 0; j < 4; j++) {
        uint16_t h0, l0, h1, l1;
        split_bf16(vv[2 * j], h0, l0);
        split_bf16(vv[2 * j + 1], h1, l1);
        hp[j] = (uint32_t)h0 | ((uint32_t)h1 << 16);
        lp[j] = (uint32_t)l0 | ((uint32_t)l1 << 16);
    }
    size_t e = (size_t)row * 256 + c8;
    *(uint4*)((uint16_t*)g_a_hi + e) = make_uint4(hp[0], hp[1], hp[2], hp[3]);
    *(uint4*)((uint16_t*)g_a_lo + e) = make_uint4(lp[0], lp[1], lp[2], lp[3]);
}

// ---------------- pipelined HMMA split-bf16 GEMM --------------------------------
// C[128x128 per CTA] = act(A[M x KDIM] @ W[KDIM x 128] + bias)
// A pre-split bf16 hi/lo; W pre-transposed split bf16 [n][k].
// C ~= Ah@Wh + Ah@Wl + Al@Wh.  2-stage cp.async double buffer, BK=32.
#define PADK 40                       // 80B row stride: 16B-aligned, ldmatrix conflict-free
#define MAT_BYTES (128 * PADK * 2)    // 10240
#define STAGE_BYTES (4 * MAT_BYTES)   // 40960
#define GSMEM (2 * STAGE_BYTES)       // 81920
#define OFF_AH 0
#define OFF_AL MAT_BYTES
#define OFF_WH (2 * MAT_BYTES)
#define OFF_WL (3 * MAT_BYTES)

template<int KDIM, bool RELU, int OMODE>   // OMODE 0: fp32 out; 1: split bf16 -> g_h
__global__ __launch_bounds__(256)
void hmma_gemm(int asel, int woff, const float* __restrict__ bias,
               float* __restrict__ Oext, int osel)
{
    extern __shared__ __align__(16) char smem[];
    const uint32_t sb = smem_u32(smem);

    const __nv_bfloat16* __restrict__ Ah = resolve_ah(asel);
    const __nv_bfloat16* __restrict__ Al = resolve_al(asel);
    const __nv_bfloat16* __restrict__ Wh = g_wh + woff;
    const __nv_bfloat16* __restrict__ Wl = g_wl + woff;

    const int tid  = threadIdx.x;
    const int lane = tid & 31;
    const int wid  = tid >> 5;
    const int wm   = (wid & 1) * 64;
    const int wn   = (wid >> 1) * 32;
    const int row0 = blockIdx.x * 128;

    float acc[4][4][4];
#pragma unroll
    for (int i = 0; i < 4; i++)
#pragma unroll
        for (int j = 0; j < 4; j++)
#pragma unroll
            for (int r = 0; r < 4; r++) acc[i][j][r] = 0.f;

    // per-thread load slots: 2 chunks of 16B per matrix per stage
    const int c0 = tid * 2;
    const int lr0 = c0 >> 2,        lc0 = (c0 & 3) << 3;
    const int lr1 = (c0 + 1) >> 2,  lc1 = ((c0 + 1) & 3) << 3;

    auto load_stage = [&](int kt, int buf) {
        uint32_t s = sb + buf * STAGE_BYTES;
        uint32_t d0 = (uint32_t)(lr0 * PADK + lc0) * 2;
        uint32_t d1 = (uint32_t)(lr1 * PADK + lc1) * 2;
        size_t gA0 = (size_t)(row0 + lr0) * KDIM + kt + lc0;
        size_t gA1 = (size_t)(row0 + lr1) * KDIM + kt + lc1;
        size_t gW0 = (size_t)lr0 * KDIM + kt + lc0;
        size_t gW1 = (size_t)lr1 * KDIM + kt + lc1;
        cp_async16(s + OFF_AH + d0, Ah + gA0);
        cp_async16(s + OFF_AH + d1, Ah + gA1);
        cp_async16(s + OFF_AL + d0, Al + gA0);
        cp_async16(s + OFF_AL + d1, Al + gA1);
        cp_async16(s + OFF_WH + d0, Wh + gW0);
        cp_async16(s + OFF_WH + d1, Wh + gW1);
        cp_async16(s + OFF_WL + d0, Wl + gW0);
        cp_async16(s + OFF_WL + d1, Wl + gW1);
    };

    const int NS = KDIM / 32;
    load_stage(0, 0);
    cp_commit();

    for (int s = 0; s < NS; s++) {
        if (s + 1 < NS) {
            load_stage((s + 1) * 32, (s + 1) & 1);
            cp_commit();
            cp_wait1();
        } else {
            cp_wait0();
        }
        __syncthreads();

        const uint32_t base = sb + (s & 1) * STAGE_BYTES;
#pragma unroll
        for (int ks = 0; ks < 2; ks++) {
            const int k0 = ks * 16;
            uint32_t fah[4][4], fal[4][4];
#pragma unroll
            for (int mi = 0; mi < 4; mi++) {
                uint32_t off = (uint32_t)((wm + mi * 16 + (lane & 15)) * PADK
                                          + k0 + ((lane >> 4) << 3)) * 2;
                ldmatrix_x4(fah[mi], base + OFF_AH + off);
                ldmatrix_x4(fal[mi], base + OFF_AL + off);
            }
            uint32_t fbh[4][2], fbl[4][2];
#pragma unroll
            for (int njp = 0; njp < 2; njp++) {
                uint32_t off = (uint32_t)((wn + njp * 16 + ((lane >> 4) << 3) + (lane & 7)) * PADK
                                          + k0 + (((lane >> 3) & 1) << 3)) * 2;
                uint32_t t[4];
                ldmatrix_x4(t, base + OFF_WH + off);
                fbh[2*njp][0] = t[0]; fbh[2*njp][1] = t[1];
                fbh[2*njp+1][0] = t[2]; fbh[2*njp+1][1] = t[3];
                ldmatrix_x4(t, base + OFF_WL + off);
                fbl[2*njp][0] = t[0]; fbl[2*njp][1] = t[1];
                fbl[2*njp+1][0] = t[2]; fbl[2*njp+1][1] = t[3];
            }
#pragma unroll
            for (int mi = 0; mi < 4; mi++)
#pragma unroll
                for (int ni = 0; ni < 4; ni++) {
                    mma_bf16(acc[mi][ni], fah[mi], fbh[ni]);
                    mma_bf16(acc[mi][ni], fah[mi], fbl[ni]);
                    mma_bf16(acc[mi][ni], fal[mi], fbh[ni]);
                }
        }
        __syncthreads();
    }

    // ---- epilogue ----
    float* out = resolve_o32(Oext, osel);
#pragma unroll
    for (int mi = 0; mi < 4; mi++) {
#pragma unroll
        for (int ni = 0; ni < 4; ni++) {
            int r0 = row0 + wm + mi * 16 + (lane >> 2);
            int c  = wn + ni * 8 + ((lane & 3) << 1);
            float b0 = bias[c], b1 = bias[c + 1];
            float v00 = acc[mi][ni][0] + b0, v01 = acc[mi][ni][1] + b1;
            float v10 = acc[mi][ni][2] + b0, v11 = acc[mi][ni][3] + b1;
            if (RELU) {
                v00 = fmaxf(v00, 0.f); v01 = fmaxf(v01, 0.f);
                v10 = fmaxf(v10, 0.f); v11 = fmaxf(v11, 0.f);
            }
            if (OMODE == 0) {
                *(float2*)&out[(size_t)r0 * 128 + c]       = make_float2(v00, v01);
                *(float2*)&out[(size_t)(r0 + 8) * 128 + c] = make_float2(v10, v11);
            } else {
                uint16_t h0, l0, h1, l1;
                split_bf16(v00, h0, l0); split_bf16(v01, h1, l1);
                *(uint32_t*)((uint16_t*)g_h_hi + (size_t)r0 * 128 + c) = (uint32_t)h0 | ((uint32_t)h1 << 16);
                *(uint32_t*)((uint16_t*)g_h_lo + (size_t)r0 * 128 + c) = (uint32_t)l0 | ((uint32_t)l1 << 16);
                split_bf16(v10, h0, l0); split_bf16(v11, h1, l1);
                *(uint32_t*)((uint16_t*)g_h_hi + (size_t)(r0 + 8) * 128 + c) = (uint32_t)h0 | ((uint32_t)h1 << 16);
                *(uint32_t*)((uint16_t*)g_h_lo + (size_t)(r0 + 8) * 128 + c) = (uint32_t)l0 | ((uint32_t)l1 << 16);
            }
        }
    }
}

// ---------------- attention: one block per (b, head, node) ----------------------
// thread t == query time p; K/V in shared; online softmax; split-bf16 output.
__global__ __launch_bounds__(128)
void attn_kernel()
{
    const int n  = blockIdx.x;
    const int bh = blockIdx.y;
    const int b  = bh >> 3;
    const int h  = bh & 7;
    const int t  = threadIdx.x;

    __shared__ float Ks[128][16];
    __shared__ float Vs[128][16];

    const size_t base = ((size_t)(b * P_) * N_ + n) * D_ + h * 16;

#pragma unroll
    for (int i = 0; i < 4; i++) {
        int id = t + i * 128;
        int r  = id >> 2;
        int d4 = (id & 3) << 2;
        size_t g = base + (size_t)r * ROWSTRIDE_ + d4;
        *(float4*)&Ks[r][d4] = *(const float4*)&g_k[g];
        *(float4*)&Vs[r][d4] = *(const float4*)&g_v[g];
    }

    float qr[16];
#pragma unroll
    for (int d4 = 0; d4 < 16; d4 += 4) {
        float4 v = *(const float4*)&g_q[base + (size_t)t * ROWSTRIDE_ + d4];
        qr[d4 + 0] = v.x; qr[d4 + 1] = v.y; qr[d4 + 2] = v.z; qr[d4 + 3] = v.w;
    }
    __syncthreads();

    float m = -1e30f, denom = 0.f;
    float o[16];
#pragma unroll
    for (int d = 0; d < 16; d++) o[d] = 0.f;

    for (int q = 0; q <= t; q++) {
        float4 k0 = *(const float4*)&Ks[q][0];
        float4 k1 = *(const float4*)&Ks[q][4];
        float4 k2 = *(const float4*)&Ks[q][8];
        float4 k3 = *(const float4*)&Ks[q][12];
        float s = qr[0] * k0.x;
        s = fmaf(qr[1],  k0.y, s); s = fmaf(qr[2],  k0.z, s); s = fmaf(qr[3],  k0.w, s);
        s = fmaf(qr[4],  k1.x, s); s = fmaf(qr[5],  k1.y, s); s = fmaf(qr[6],  k1.z, s); s = fmaf(qr[7],  k1.w, s);
        s = fmaf(qr[8],  k2.x, s); s = fmaf(qr[9],  k2.y, s); s = fmaf(qr[10], k2.z, s); s = fmaf(qr[11], k2.w, s);
        s = fmaf(qr[12], k3.x, s); s = fmaf(qr[13], k3.y, s); s = fmaf(qr[14], k3.z, s); s = fmaf(qr[15], k3.w, s);
        s *= 0.25f;

        if (s > m) {
            float scale = __expf(m - s);
            denom *= scale;
#pragma unroll
            for (int d = 0; d < 16; d++) o[d] *= scale;
            m = s;
        }
        float w = __expf(s - m);
        denom += w;

        float4 v0 = *(const float4*)&Vs[q][0];
        float4 v1 = *(const float4*)&Vs[q][4];
        float4 v2 = *(const float4*)&Vs[q][8];
        float4 v3 = *(const float4*)&Vs[q][12];
        o[0]  = fmaf(w, v0.x, o[0]);  o[1]  = fmaf(w, v0.y, o[1]);
        o[2]  = fmaf(w, v0.z, o[2]);  o[3]  = fmaf(w, v0.w, o[3]);
        o[4]  = fmaf(w, v1.x, o[4]);  o[5]  = fmaf(w, v1.y, o[5]);
        o[6]  = fmaf(w, v1.z, o[6]);  o[7]  = fmaf(w, v1.w, o[7]);
        o[8]  = fmaf(w, v2.x, o[8]);  o[9]  = fmaf(w, v2.y, o[9]);
        o[10] = fmaf(w, v2.z, o[10]); o[11] = fmaf(w, v2.w, o[11]);
        o[12] = fmaf(w, v3.x, o[12]); o[13] = fmaf(w, v3.y, o[13]);
        o[14] = fmaf(w, v3.z, o[14]); o[15] = fmaf(w, v3.w, o[15]);
    }

    float inv = 1.f / denom;
    size_t ob = base + (size_t)t * ROWSTRIDE_;
    uint32_t hp[8], lp[8];
#pragma unroll
    for (int j = 0; j < 8; j++) {
        uint16_t h0, l0, h1, l1;
        split_bf16(o[2 * j] * inv, h0, l0);
        split_bf16(o[2 * j + 1] * inv, h1, l1);
        hp[j] = (uint32_t)h0 | ((uint32_t)h1 << 16);
        lp[j] = (uint32_t)l0 | ((uint32_t)l1 << 16);
    }
    *(uint4*)((uint16_t*)g_att_hi + ob)     = make_uint4(hp[0], hp[1], hp[2], hp[3]);
    *(uint4*)((uint16_t*)g_att_hi + ob + 8) = make_uint4(hp[4], hp[5], hp[6], hp[7]);
    *(uint4*)((uint16_t*)g_att_lo + ob)     = make_uint4(lp[0], lp[1], lp[2], lp[3]);
    *(uint4*)((uint16_t*)g_att_lo + ob + 8) = make_uint4(lp[4], lp[5], lp[6], lp[7]);
}

// ---------------- launch -------------------------------------------------------
extern "C" void kernel_launch(void* const* d_in, const int* in_sizes, int n_in,
                              void* d_out, int out_size)
{
    const float* X   = (const float*)d_in[0];
    const float* STE = (const float*)d_in[1];
    const float* Wq  = (const float*)d_in[2];
    const float* bq  = (const float*)d_in[3];
    const float* Wk  = (const float*)d_in[4];
    const float* bk  = (const float*)d_in[5];
    const float* Wv  = (const float*)d_in[6];
    const float* bv  = (const float*)d_in[7];
    const float* W1  = (const float*)d_in[8];
    const float* b1  = (const float*)d_in[9];
    const float* W2  = (const float*)d_in[10];
    const float* b2  = (const float*)d_in[11];
    float* out = (float*)d_out;

    cudaFuncSetAttribute(hmma_gemm<256, true, 0>,  cudaFuncAttributeMaxDynamicSharedMemorySize, GSMEM);
    cudaFuncSetAttribute(hmma_gemm<128, true, 1>,  cudaFuncAttributeMaxDynamicSharedMemorySize, GSMEM);
    cudaFuncSetAttribute(hmma_gemm<128, false, 0>, cudaFuncAttributeMaxDynamicSharedMemorySize, GSMEM);

    const int nblk = M_ / 128;   // 2048

    // preprocessing: weight transpose+split, activation concat+split
    convert_w<<<512, 256>>>(Wq, Wk, Wv, W1, W2);
    convert_a<<<32768, 256>>>(X, STE);

    // QKV projections (pipelined HMMA, bf16x3)
    hmma_gemm<256, true, 0><<<nblk, 256, GSMEM>>>(0, 0,      bq, nullptr, 0);
    hmma_gemm<256, true, 0><<<nblk, 256, GSMEM>>>(0, 32768,  bk, nullptr, 1);
    hmma_gemm<256, true, 0><<<nblk, 256, GSMEM>>>(0, 65536,  bv, nullptr, 2);

    // causal attention per (b, head, node)
    attn_kernel<<<dim3(N_, B_ * 8), 128>>>();

    // output MLP
    hmma_gemm<128, true, 1><<<nblk, 256, GSMEM>>>(1, 98304,  b1, nullptr, -1);
    hmma_gemm<128, false, 0><<<nblk, 256, GSMEM>>>(2, 114688, b2, out, -1);
}

// round 9
// speedup vs baseline: 2.1019x; 1.0953x over previous
#include <cuda_runtime.h>
#include <cuda_bf16.h>
#include <math.h>
#include <stdint.h>

#define B_   8
#define P_   128
#define N_   256
#define D_   128
#define M_   (B_*P_*N_)        // 262144 rows
#define ROWSTRIDE_ (N_*D_)     // 32768 floats between consecutive p for fixed (b,n)

// ---------------- scratch (device globals; no allocation allowed) ----------------
__device__ __align__(16) __nv_bfloat16 g_a_hi[(size_t)M_ * 256];
__device__ __align__(16) __nv_bfloat16 g_a_lo[(size_t)M_ * 256];
__device__ float g_q[(size_t)M_ * D_];
__device__ float g_k[(size_t)M_ * D_];
__device__ float g_v[(size_t)M_ * D_];
__device__ __align__(16) __nv_bfloat16 g_att_hi[(size_t)M_ * D_];
__device__ __align__(16) __nv_bfloat16 g_att_lo[(size_t)M_ * D_];
// weights transposed to [n][k], bf16-split. layout: Wq(32768) Wk Wv W1(16384) W2
__device__ __align__(16) __nv_bfloat16 g_wh[131072];
__device__ __align__(16) __nv_bfloat16 g_wl[131072];

// ---------------- helpers ----------------
__device__ __forceinline__ uint32_t smem_u32(const void* p) {
    uint32_t a;
    asm("{ .reg .u64 t; cvta.to.shared.u64 t, %1; cvt.u32.u64 %0, t; }" : "=r"(a) : "l"(p));
    return a;
}
__device__ __forceinline__ void split_bf16(float x, uint16_t& h, uint16_t& l) {
    __nv_bfloat16 hb = __float2bfloat16(x);
    __nv_bfloat16 lb = __float2bfloat16(x - __bfloat162float(hb));
    h = __bfloat16_as_ushort(hb);
    l = __bfloat16_as_ushort(lb);
}
__device__ __forceinline__ void ldmatrix_x4(uint32_t* r, uint32_t addr) {
    asm volatile("ldmatrix.sync.aligned.m8n8.x4.shared.b16 {%0,%1,%2,%3}, [%4];"
                 : "=r"(r[0]), "=r"(r[1]), "=r"(r[2]), "=r"(r[3]) : "r"(addr));
}
__device__ __forceinline__ void mma_bf16(float* d, const uint32_t* a, const uint32_t* b) {
    asm volatile(
        "mma.sync.aligned.m16n8k16.row.col.f32.bf16.bf16.f32 "
        "{%0,%1,%2,%3}, {%4,%5,%6,%7}, {%8,%9}, {%0,%1,%2,%3};"
        : "+f"(d[0]), "+f"(d[1]), "+f"(d[2]), "+f"(d[3])
        : "r"(a[0]), "r"(a[1]), "r"(a[2]), "r"(a[3]), "r"(b[0]), "r"(b[1]));
}
__device__ __forceinline__ void cp_async16(uint32_t dst, const void* src) {
    asm volatile("cp.async.cg.shared.global [%0], [%1], 16;" :: "r"(dst), "l"(src));
}
__device__ __forceinline__ void cp_commit() {
    asm volatile("cp.async.commit_group;" ::: "memory");
}
__device__ __forceinline__ void cp_wait0() {
    asm volatile("cp.async.wait_group 0;" ::: "memory");
}

// ---------------- convert weights: W[k][n] fp32 -> transposed split bf16 ----------
__global__ void convert_w(const float* __restrict__ Wq, const float* __restrict__ Wk,
                          const float* __restrict__ Wv, const float* __restrict__ W1,
                          const float* __restrict__ W2)
{
    int id = blockIdx.x * 256 + threadIdx.x;      // < 131072
    const float* src; int K, n, k; size_t dofs;
    if (id < 98304) {
        int wi = id >> 15, rem = id & 32767;
        k = rem >> 7; n = rem & 127; K = 256;
        src = (wi == 0) ? Wq : (wi == 1) ? Wk : Wv;
        dofs = (size_t)wi * 32768;
    } else {
        int r2 = id - 98304;
        int wi = r2 >> 14, rem = r2 & 16383;
        k = rem >> 7; n = rem & 127; K = 128;
        src = wi ? W2 : W1;
        dofs = 98304 + (size_t)wi * 16384;
    }
    float x = src[(size_t)k * 128 + n];
    uint16_t h, l;
    split_bf16(x, h, l);
    size_t d = dofs + (size_t)n * K + k;
    ((uint16_t*)g_wh)[d] = h;
    ((uint16_t*)g_wl)[d] = l;
}

// ---------------- convert activations: concat(X,STE) -> split bf16 [M x 256] -----
__global__ void convert_a(const float* __restrict__ X, const float* __restrict__ STE)
{
    size_t id = (size_t)blockIdx.x * 256 + threadIdx.x;   // one per 8 elements
    int row = (int)(id >> 5);
    int c8  = (int)(id & 31) << 3;
    const float* src = (c8 < 128) ? (X + (size_t)row * 128 + c8)
                                  : (STE + (size_t)row * 128 + (c8 - 128));
    float4 v0 = ((const float4*)src)[0];
    float4 v1 = ((const float4*)src)[1];
    float vv[8] = {v0.x, v0.y, v0.z, v0.w, v1.x, v1.y, v1.z, v1.w};
    uint32_t hp[4], lp[4];
#pragma unroll
    for (int j = 0; j < 4; j++) {
        uint16_t h0, l0, h1, l1;
        split_bf16(vv[2 * j], h0, l0);
        split_bf16(vv[2 * j + 1], h1, l1);
        hp[j] = (uint32_t)h0 | ((uint32_t)h1 << 16);
        lp[j] = (uint32_t)l0 | ((uint32_t)l1 << 16);
    }
    size_t e = (size_t)row * 256 + c8;
    *(uint4*)((uint16_t*)g_a_hi + e) = make_uint4(hp[0], hp[1], hp[2], hp[3]);
    *(uint4*)((uint16_t*)g_a_lo + e) = make_uint4(lp[0], lp[1], lp[2], lp[3]);
}

// ---------------- shared GEMM tile constants ------------------------------------
#define PADK 40                       // 80B row stride: 16B-aligned, ldmatrix conflict-free
#define MAT_BYTES (128 * PADK * 2)    // 10240
#define STAGE_BYTES (4 * MAT_BYTES)   // 40960
#define OFF_AH 0
#define OFF_AL MAT_BYTES
#define OFF_WH (2 * MAT_BYTES)
#define OFF_WL (3 * MAT_BYTES)
#define QKV_SMEM (2 * STAGE_BYTES)            // 81920
#define MLP_SMEM (2 * STAGE_BYTES + 20480)    // 102400 (H chunks reuse stage bufs; +W2 stage)

// fragment loaders (shared by all GEMM mainloops)
__device__ __forceinline__ void load_a_frags(uint32_t base_h, uint32_t base_l,
                                             int wm, int lane, int k0,
                                             uint32_t fah[4][4], uint32_t fal[4][4]) {
#pragma unroll
    for (int mi = 0; mi < 4; mi++) {
        uint32_t off = (uint32_t)((wm + mi * 16 + (lane & 15)) * PADK
                                  + k0 + ((lane >> 4) << 3)) * 2;
        ldmatrix_x4(fah[mi], base_h + off);
        ldmatrix_x4(fal[mi], base_l + off);
    }
}
__device__ __forceinline__ void load_b_frags(uint32_t base_h, uint32_t base_l,
                                             int wn, int lane, int k0,
                                             uint32_t fbh[4][2], uint32_t fbl[4][2]) {
#pragma unroll
    for (int njp = 0; njp < 2; njp++) {
        uint32_t off = (uint32_t)((wn + njp * 16 + ((lane >> 4) << 3) + (lane & 7)) * PADK
                                  + k0 + (((lane >> 3) & 1) << 3)) * 2;
        uint32_t t[4];
        ldmatrix_x4(t, base_h + off);
        fbh[2*njp][0] = t[0]; fbh[2*njp][1] = t[1];
        fbh[2*njp+1][0] = t[2]; fbh[2*njp+1][1] = t[3];
        ldmatrix_x4(t, base_l + off);
        fbl[2*njp][0] = t[0]; fbl[2*njp][1] = t[1];
        fbl[2*njp+1][0] = t[2]; fbl[2*njp+1][1] = t[3];
    }
}
__device__ __forceinline__ void mma_block(float acc[4][4][4],
                                          uint32_t fah[4][4], uint32_t fal[4][4],
                                          uint32_t fbh[4][2], uint32_t fbl[4][2]) {
#pragma unroll
    for (int mi = 0; mi < 4; mi++)
#pragma unroll
        for (int ni = 0; ni < 4; ni++) {
            mma_bf16(acc[mi][ni], fah[mi], fbh[ni]);
            mma_bf16(acc[mi][ni], fah[mi], fbl[ni]);
            mma_bf16(acc[mi][ni], fal[mi], fbh[ni]);
        }
}

// ---------------- fused QKV GEMM -------------------------------------------------
// grid (3, 2048): x = which weight (Wq/Wk/Wv) -> consecutive CTAs share the A tile
// (L2 hits), y = row block. C = relu(A[128x256] @ W + b) -> fp32 g_q/g_k/g_v.
__global__ __launch_bounds__(256)
void qkv_gemm(const float* __restrict__ bq, const float* __restrict__ bk,
              const float* __restrict__ bv)
{
    extern __shared__ __align__(16) char smem[];
    const uint32_t sb = smem_u32(smem);

    const int wsel = blockIdx.x;
    const int row0 = blockIdx.y * 128;
    const __nv_bfloat16* __restrict__ Ah = g_a_hi;
    const __nv_bfloat16* __restrict__ Al = g_a_lo;
    const __nv_bfloat16* __restrict__ Wh = g_wh + wsel * 32768;
    const __nv_bfloat16* __restrict__ Wl = g_wl + wsel * 32768;
    const float* __restrict__ bias = (wsel == 0) ? bq : (wsel == 1) ? bk : bv;
    float* __restrict__ out = (wsel == 0) ? g_q : (wsel == 1) ? g_k : g_v;

    const int tid  = threadIdx.x;
    const int lane = tid & 31;
    const int wid  = tid >> 5;
    const int wm   = (wid & 1) * 64;
    const int wn   = (wid >> 1) * 32;

    float acc[4][4][4];
#pragma unroll
    for (int i = 0; i < 4; i++)
#pragma unroll
        for (int j = 0; j < 4; j++)
#pragma unroll
            for (int r = 0; r < 4; r++) acc[i][j][r] = 0.f;

    const int c0 = tid * 2;
    const int lr0 = c0 >> 2,        lc0 = (c0 & 3) << 3;
    const int lr1 = (c0 + 1) >> 2,  lc1 = ((c0 + 1) & 3) << 3;

    auto load_stage = [&](int kt, int buf) {
        uint32_t s = sb + buf * STAGE_BYTES;
        uint32_t d0 = (uint32_t)(lr0 * PADK + lc0) * 2;
        uint32_t d1 = (uint32_t)(lr1 * PADK + lc1) * 2;
        size_t gA0 = (size_t)(row0 + lr0) * 256 + kt + lc0;
        size_t gA1 = (size_t)(row0 + lr1) * 256 + kt + lc1;
        size_t gW0 = (size_t)lr0 * 256 + kt + lc0;
        size_t gW1 = (size_t)lr1 * 256 + kt + lc1;
        cp_async16(s + OFF_AH + d0, Ah + gA0);
        cp_async16(s + OFF_AH + d1, Ah + gA1);
        cp_async16(s + OFF_AL + d0, Al + gA0);
        cp_async16(s + OFF_AL + d1, Al + gA1);
        cp_async16(s + OFF_WH + d0, Wh + gW0);
        cp_async16(s + OFF_WH + d1, Wh + gW1);
        cp_async16(s + OFF_WL + d0, Wl + gW0);
        cp_async16(s + OFF_WL + d1, Wl + gW1);
    };

    const int NS = 8;   // 256 / 32
    load_stage(0, 0);
    cp_commit();

    for (int s = 0; s < NS; s++) {
        cp_wait0();
        __syncthreads();                 // stage s visible; all warps done with s-1
        if (s + 1 < NS) { load_stage((s + 1) * 32, (s + 1) & 1); cp_commit(); }

        const uint32_t base = sb + (s & 1) * STAGE_BYTES;
#pragma unroll
        for (int ks = 0; ks < 2; ks++) {
            const int k0 = ks * 16;
            uint32_t fah[4][4], fal[4][4], fbh[4][2], fbl[4][2];
            load_a_frags(base + OFF_AH, base + OFF_AL, wm, lane, k0, fah, fal);
            load_b_frags(base + OFF_WH, base + OFF_WL, wn, lane, k0, fbh, fbl);
            mma_block(acc, fah, fal, fbh, fbl);
        }
    }

    // epilogue: bias + relu, fp32 out
#pragma unroll
    for (int mi = 0; mi < 4; mi++) {
#pragma unroll
        for (int ni = 0; ni < 4; ni++) {
            int r0 = row0 + wm + mi * 16 + (lane >> 2);
            int c  = wn + ni * 8 + ((lane & 3) << 1);
            float b0 = bias[c], b1 = bias[c + 1];
            float v00 = fmaxf(acc[mi][ni][0] + b0, 0.f), v01 = fmaxf(acc[mi][ni][1] + b1, 0.f);
            float v10 = fmaxf(acc[mi][ni][2] + b0, 0.f), v11 = fmaxf(acc[mi][ni][3] + b1, 0.f);
            *(float2*)&out[(size_t)r0 * 128 + c]       = make_float2(v00, v01);
            *(float2*)&out[(size_t)(r0 + 8) * 128 + c] = make_float2(v10, v11);
        }
    }
}

// ---------------- fused MLP: out = relu(att@W1+b1)@W2 + b2 ----------------------
// Phase 1: h-tile [128x128] via pipelined GEMM (A = g_att split bf16), h staged
// split-bf16 in SMEM (reusing the stage buffers). Phase 2: h@W2 from SMEM.
__global__ __launch_bounds__(256)
void mlp_fused(const float* __restrict__ b1, const float* __restrict__ b2,
               float* __restrict__ out)
{
    extern __shared__ __align__(16) char smem[];
    const uint32_t sb = smem_u32(smem);

    const __nv_bfloat16* __restrict__ Ah = g_att_hi;
    const __nv_bfloat16* __restrict__ Al = g_att_lo;
    const __nv_bfloat16* __restrict__ W1h = g_wh + 98304;
    const __nv_bfloat16* __restrict__ W1l = g_wl + 98304;
    const __nv_bfloat16* __restrict__ W2h = g_wh + 114688;
    const __nv_bfloat16* __restrict__ W2l = g_wl + 114688;

    const int tid  = threadIdx.x;
    const int lane = tid & 31;
    const int wid  = tid >> 5;
    const int wm   = (wid & 1) * 64;
    const int wn   = (wid >> 1) * 32;
    const int row0 = blockIdx.x * 128;

    const int c0 = tid * 2;
    const int lr0 = c0 >> 2,        lc0 = (c0 & 3) << 3;
    const int lr1 = (c0 + 1) >> 2,  lc1 = ((c0 + 1) & 3) << 3;

    float acc[4][4][4];
#pragma unroll
    for (int i = 0; i < 4; i++)
#pragma unroll
        for (int j = 0; j < 4; j++)
#pragma unroll
            for (int r = 0; r < 4; r++) acc[i][j][r] = 0.f;

    // ---- phase 1: h = relu(att @ W1 + b1) ----
    auto load_stage1 = [&](int kt, int buf) {
        uint32_t s = sb + buf * STAGE_BYTES;
        uint32_t d0 = (uint32_t)(lr0 * PADK + lc0) * 2;
        uint32_t d1 = (uint32_t)(lr1 * PADK + lc1) * 2;
        size_t gA0 = (size_t)(row0 + lr0) * 128 + kt + lc0;
        size_t gA1 = (size_t)(row0 + lr1) * 128 + kt + lc1;
        size_t gW0 = (size_t)lr0 * 128 + kt + lc0;
        size_t gW1 = (size_t)lr1 * 128 + kt + lc1;
        cp_async16(s + OFF_AH + d0, Ah + gA0);
        cp_async16(s + OFF_AH + d1, Ah + gA1);
        cp_async16(s + OFF_AL + d0, Al + gA0);
        cp_async16(s + OFF_AL + d1, Al + gA1);
        cp_async16(s + OFF_WH + d0, W1h + gW0);
        cp_async16(s + OFF_WH + d1, W1h + gW1);
        cp_async16(s + OFF_WL + d0, W1l + gW0);
        cp_async16(s + OFF_WL + d1, W1l + gW1);
    };

    load_stage1(0, 0);
    cp_commit();
    for (int s = 0; s < 4; s++) {
        cp_wait0();
        __syncthreads();
        if (s + 1 < 4) { load_stage1((s + 1) * 32, (s + 1) & 1); cp_commit(); }
        const uint32_t base = sb + (s & 1) * STAGE_BYTES;
#pragma unroll
        for (int ks = 0; ks < 2; ks++) {
            const int k0 = ks * 16;
            uint32_t fah[4][4], fal[4][4], fbh[4][2], fbl[4][2];
            load_a_frags(base + OFF_AH, base + OFF_AL, wm, lane, k0, fah, fal);
            load_b_frags(base + OFF_WH, base + OFF_WL, wn, lane, k0, fbh, fbl);
            mma_block(acc, fah, fal, fbh, fbl);
        }
    }
    __syncthreads();   // all warps done reading stage buffers before H overwrites them

    // write h (relu + b1, split bf16) into SMEM H chunks:
    // chunk kc (k-cols kc*32..kc*32+31): hi at sb + kc*2*MAT_BYTES, lo at +MAT_BYTES
#pragma unroll
    for (int mi = 0; mi < 4; mi++) {
#pragma unroll
        for (int ni = 0; ni < 4; ni++) {
            int r  = wm + mi * 16 + (lane >> 2);       // local row
            int c  = wn + ni * 8 + ((lane & 3) << 1);
            int kc = c >> 5, cc = c & 31;
            uint32_t hbase = sb + (uint32_t)kc * (2 * MAT_BYTES);
            float b0 = b1[c], bb1 = b1[c + 1];
            float v00 = fmaxf(acc[mi][ni][0] + b0, 0.f), v01 = fmaxf(acc[mi][ni][1] + bb1, 0.f);
            float v10 = fmaxf(acc[mi][ni][2] + b0, 0.f), v11 = fmaxf(acc[mi][ni][3] + bb1, 0.f);
            uint16_t h0, l0, h1, l1;
            split_bf16(v00, h0, l0); split_bf16(v01, h1, l1);
            asm volatile("st.shared.b32 [%0], %1;" :: "r"(hbase + (uint32_t)(r * PADK + cc) * 2),
                         "r"((uint32_t)h0 | ((uint32_t)h1 << 16)) : "memory");
            asm volatile("st.shared.b32 [%0], %1;" :: "r"(hbase + MAT_BYTES + (uint32_t)(r * PADK + cc) * 2),
                         "r"((uint32_t)l0 | ((uint32_t)l1 << 16)) : "memory");
            split_bf16(v10, h0, l0); split_bf16(v11, h1, l1);
            asm volatile("st.shared.b32 [%0], %1;" :: "r"(hbase + (uint32_t)((r + 8) * PADK + cc) * 2),
                         "r"((uint32_t)h0 | ((uint32_t)h1 << 16)) : "memory");
            asm volatile("st.shared.b32 [%0], %1;" :: "r"(hbase + MAT_BYTES + (uint32_t)((r + 8) * PADK + cc) * 2),
                         "r"((uint32_t)l0 | ((uint32_t)l1 << 16)) : "memory");
        }
    }

    // ---- phase 2: out = h @ W2 + b2 ----
#pragma unroll
    for (int i = 0; i < 4; i++)
#pragma unroll
        for (int j = 0; j < 4; j++)
#pragma unroll
            for (int r = 0; r < 4; r++) acc[i][j][r] = 0.f;

    const uint32_t w2base = sb + 2 * STAGE_BYTES;   // 20480B: [W2h | W2l] single buffer
    for (int kc = 0; kc < 4; kc++) {
        // load W2 chunk (single-buffered; W2 is L2-resident)
        {
            uint32_t d0 = (uint32_t)(lr0 * PADK + lc0) * 2;
            uint32_t d1 = (uint32_t)(lr1 * PADK + lc1) * 2;
            size_t gW0 = (size_t)lr0 * 128 + kc * 32 + lc0;
            size_t gW1 = (size_t)lr1 * 128 + kc * 32 + lc1;
            cp_async16(w2base + d0,             W2h + gW0);
            cp_async16(w2base + d1,             W2h + gW1);
            cp_async16(w2base + MAT_BYTES + d0, W2l + gW0);
            cp_async16(w2base + MAT_BYTES + d1, W2l + gW1);
        }
        cp_commit();
        cp_wait0();
        __syncthreads();   // W2 chunk ready; (kc=0) also orders H writes before reads

        const uint32_t hbase = sb + (uint32_t)kc * (2 * MAT_BYTES);
#pragma unroll
        for (int ks = 0; ks < 2; ks++) {
            const int k0 = ks * 16;
            uint32_t fah[4][4], fal[4][4], fbh[4][2], fbl[4][2];
            load_a_frags(hbase, hbase + MAT_BYTES, wm, lane, k0, fah, fal);
            load_b_frags(w2base, w2base + MAT_BYTES, wn, lane, k0, fbh, fbl);
            mma_block(acc, fah, fal, fbh, fbl);
        }
        __syncthreads();   // done reading W2 buffer before next chunk overwrites
    }

    // epilogue: + b2, fp32 out
#pragma unroll
    for (int mi = 0; mi < 4; mi++) {
#pragma unroll
        for (int ni = 0; ni < 4; ni++) {
            int r0 = row0 + wm + mi * 16 + (lane >> 2);
            int c  = wn + ni * 8 + ((lane & 3) << 1);
            float b0 = b2[c], bb1 = b2[c + 1];
            *(float2*)&out[(size_t)r0 * 128 + c] =
                make_float2(acc[mi][ni][0] + b0, acc[mi][ni][1] + bb1);
            *(float2*)&out[(size_t)(r0 + 8) * 128 + c] =
                make_float2(acc[mi][ni][2] + b0, acc[mi][ni][3] + bb1);
        }
    }
}

// ---------------- attention: one block per (b, head, node) ----------------------
// thread t == query time p; K/V in shared; online softmax; split-bf16 output.
__global__ __launch_bounds__(128)
void attn_kernel()
{
    const int n  = blockIdx.x;
    const int bh = blockIdx.y;
    const int b  = bh >> 3;
    const int h  = bh & 7;
    const int t  = threadIdx.x;

    __shared__ float Ks[128][16];
    __shared__ float Vs[128][16];

    const size_t base = ((size_t)(b * P_) * N_ + n) * D_ + h * 16;

#pragma unroll
    for (int i = 0; i < 4; i++) {
        int id = t + i * 128;
        int r  = id >> 2;
        int d4 = (id & 3) << 2;
        size_t g = base + (size_t)r * ROWSTRIDE_ + d4;
        *(float4*)&Ks[r][d4] = *(const float4*)&g_k[g];
        *(float4*)&Vs[r][d4] = *(const float4*)&g_v[g];
    }

    float qr[16];
#pragma unroll
    for (int d4 = 0; d4 < 16; d4 += 4) {
        float4 v = *(const float4*)&g_q[base + (size_t)t * ROWSTRIDE_ + d4];
        qr[d4 + 0] = v.x; qr[d4 + 1] = v.y; qr[d4 + 2] = v.z; qr[d4 + 3] = v.w;
    }
    __syncthreads();

    float m = -1e30f, denom = 0.f;
    float o[16];
#pragma unroll
    for (int d = 0; d < 16; d++) o[d] = 0.f;

    for (int q = 0; q <= t; q++) {
        float4 k0 = *(const float4*)&Ks[q][0];
        float4 k1 = *(const float4*)&Ks[q][4];
        float4 k2 = *(const float4*)&Ks[q][8];
        float4 k3 = *(const float4*)&Ks[q][12];
        float s = qr[0] * k0.x;
        s = fmaf(qr[1],  k0.y, s); s = fmaf(qr[2],  k0.z, s); s = fmaf(qr[3],  k0.w, s);
        s = fmaf(qr[4],  k1.x, s); s = fmaf(qr[5],  k1.y, s); s = fmaf(qr[6],  k1.z, s); s = fmaf(qr[7],  k1.w, s);
        s = fmaf(qr[8],  k2.x, s); s = fmaf(qr[9],  k2.y, s); s = fmaf(qr[10], k2.z, s); s = fmaf(qr[11], k2.w, s);
        s = fmaf(qr[12], k3.x, s); s = fmaf(qr[13], k3.y, s); s = fmaf(qr[14], k3.z, s); s = fmaf(qr[15], k3.w, s);
        s *= 0.25f;

        if (s > m) {
            float scale = __expf(m - s);
            denom *= scale;
#pragma unroll
            for (int d = 0; d < 16; d++) o[d] *= scale;
            m = s;
        }
        float w = __expf(s - m);
        denom += w;

        float4 v0 = *(const float4*)&Vs[q][0];
        float4 v1 = *(const float4*)&Vs[q][4];
        float4 v2 = *(const float4*)&Vs[q][8];
        float4 v3 = *(const float4*)&Vs[q][12];
        o[0]  = fmaf(w, v0.x, o[0]);  o[1]  = fmaf(w, v0.y, o[1]);
        o[2]  = fmaf(w, v0.z, o[2]);  o[3]  = fmaf(w, v0.w, o[3]);
        o[4]  = fmaf(w, v1.x, o[4]);  o[5]  = fmaf(w, v1.y, o[5]);
        o[6]  = fmaf(w, v1.z, o[6]);  o[7]  = fmaf(w, v1.w, o[7]);
        o[8]  = fmaf(w, v2.x, o[8]);  o[9]  = fmaf(w, v2.y, o[9]);
        o[10] = fmaf(w, v2.z, o[10]); o[11] = fmaf(w, v2.w, o[11]);
        o[12] = fmaf(w, v3.x, o[12]); o[13] = fmaf(w, v3.y, o[13]);
        o[14] = fmaf(w, v3.z, o[14]); o[15] = fmaf(w, v3.w, o[15]);
    }

    float inv = 1.f / denom;
    size_t ob = base + (size_t)t * ROWSTRIDE_;
    uint32_t hp[8], lp[8];
#pragma unroll
    for (int j = 0; j < 8; j++) {
        uint16_t h0, l0, h1, l1;
        split_bf16(o[2 * j] * inv, h0, l0);
        split_bf16(o[2 * j + 1] * inv, h1, l1);
        hp[j] = (uint32_t)h0 | ((uint32_t)h1 << 16);
        lp[j] = (uint32_t)l0 | ((uint32_t)l1 << 16);
    }
    *(uint4*)((uint16_t*)g_att_hi + ob)     = make_uint4(hp[0], hp[1], hp[2], hp[3]);
    *(uint4*)((uint16_t*)g_att_hi + ob + 8) = make_uint4(hp[4], hp[5], hp[6], hp[7]);
    *(uint4*)((uint16_t*)g_att_lo + ob)     = make_uint4(lp[0], lp[1], lp[2], lp[3]);
    *(uint4*)((uint16_t*)g_att_lo + ob + 8) = make_uint4(lp[4], lp[5], lp[6], lp[7]);
}

// ---------------- launch -------------------------------------------------------
extern "C" void kernel_launch(void* const* d_in, const int* in_sizes, int n_in,
                              void* d_out, int out_size)
{
    const float* X   = (const float*)d_in[0];
    const float* STE = (const float*)d_in[1];
    const float* Wq  = (const float*)d_in[2];
    const float* bq  = (const float*)d_in[3];
    const float* Wk  = (const float*)d_in[4];
    const float* bk  = (const float*)d_in[5];
    const float* Wv  = (const float*)d_in[6];
    const float* bv  = (const float*)d_in[7];
    const float* W1  = (const float*)d_in[8];
    const float* b1  = (const float*)d_in[9];
    const float* W2  = (const float*)d_in[10];
    const float* b2  = (const float*)d_in[11];
    float* out = (float*)d_out;

    cudaFuncSetAttribute(qkv_gemm,  cudaFuncAttributeMaxDynamicSharedMemorySize, QKV_SMEM);
    cudaFuncSetAttribute(mlp_fused, cudaFuncAttributeMaxDynamicSharedMemorySize, MLP_SMEM);

    // preprocessing: weight transpose+split, activation concat+split
    convert_w<<<512, 256>>>(Wq, Wk, Wv, W1, W2);
    convert_a<<<32768, 256>>>(X, STE);

    // fused QKV projections (x = weight select -> L2-shared A tiles)
    qkv_gemm<<<dim3(3, M_ / 128), 256, QKV_SMEM>>>(bq, bk, bv);

    // causal attention per (b, head, node)
    attn_kernel<<<dim3(N_, B_ * 8), 128>>>();

    // fused output MLP
    mlp_fused<<<M_ / 128, 256, MLP_SMEM>>>(b1, b2, out);
}